// round 2
// baseline (speedup 1.0000x reference)
#include <cuda_runtime.h>
#include <cuda_bf16.h>

#define GAMA 1.0f

__global__ void prl_init_out(float* out) { *out = 0.0f; }

// One block per row. Closed-form pairwise ranking loss:
//   p = sigmoid(x); since p in [0,1] and GAMA=1, relu(1 + p_i - p_j) == 1 + p_i - p_j always.
//   row loss = c0*c1*GAMA + c1*S0 - c0*S1
__global__ __launch_bounds__(256) void prl_row_kernel(
    const float* __restrict__ logit,
    const int*   __restrict__ label,
    float* __restrict__ out,
    int L)
{
    const int b = blockIdx.x;
    const float* row_x = logit + (size_t)b * L;
    const int*   row_y = label + (size_t)b * L;

    float s0 = 0.0f, s1 = 0.0f, c0 = 0.0f;

    for (int i = threadIdx.x; i < L; i += blockDim.x) {
        float x = row_x[i];
        int   y = row_y[i];
        float p = 1.0f / (1.0f + __expf(-x));
        if (y == 0) { s0 += p; c0 += 1.0f; }
        else        { s1 += p; }
    }

    // warp reduce
    #pragma unroll
    for (int off = 16; off > 0; off >>= 1) {
        s0 += __shfl_down_sync(0xFFFFFFFFu, s0, off);
        s1 += __shfl_down_sync(0xFFFFFFFFu, s1, off);
        c0 += __shfl_down_sync(0xFFFFFFFFu, c0, off);
    }

    __shared__ float sh0[8], sh1[8], shc[8];
    const int wid = threadIdx.x >> 5;
    const int lid = threadIdx.x & 31;
    if (lid == 0) { sh0[wid] = s0; sh1[wid] = s1; shc[wid] = c0; }
    __syncthreads();

    if (wid == 0) {
        const int nw = blockDim.x >> 5;
        s0 = (lid < nw) ? sh0[lid] : 0.0f;
        s1 = (lid < nw) ? sh1[lid] : 0.0f;
        c0 = (lid < nw) ? shc[lid] : 0.0f;
        #pragma unroll
        for (int off = 4; off > 0; off >>= 1) {
            s0 += __shfl_down_sync(0xFFFFFFFFu, s0, off);
            s1 += __shfl_down_sync(0xFFFFFFFFu, s1, off);
            c0 += __shfl_down_sync(0xFFFFFFFFu, c0, off);
        }
        if (lid == 0) {
            float c1 = (float)L - c0;
            float loss = c0 * c1 * GAMA + c1 * s0 - c0 * s1;
            atomicAdd(out, loss);
        }
    }
}

extern "C" void kernel_launch(void* const* d_in, const int* in_sizes, int n_in,
                              void* d_out, int out_size)
{
    const float* logit = (const float*)d_in[0];
    const int*   label = (const int*)d_in[1];
    float* out = (float*)d_out;

    const int L = 1024;
    const int total = in_sizes[0];
    const int B = total / L;

    prl_init_out<<<1, 1>>>(out);
    prl_row_kernel<<<B, 256>>>(logit, label, out, L);
}

// round 5
// speedup vs baseline: 1.3413x; 1.3413x over previous
#include <cuda_runtime.h>
#include <cuda_bf16.h>

#define GAMA 1.0f
#define ROW_L 1024
#define THREADS 256

// Self-resetting cross-block accumulator (module-load init = 0; the last
// finishing block writes the result and restores the zero state, so every
// graph replay sees clean scratch).
__device__ float        g_partial = 0.0f;
__device__ unsigned int g_ticket  = 0u;

// One block per row (L=1024, 256 threads -> exactly one float4 + one int4 per
// thread). Closed form: p = sigmoid(x) in [0,1], GAMA=1 => the ReLU is always
// identity for neg-pos pairs, so
//   row loss = c0*c1*GAMA + c1*S0 - c0*S1,  S0 = S - S1, c0 = L - c1.
__global__ __launch_bounds__(THREADS) void prl_kernel(
    const float4* __restrict__ logit4,
    const int4*   __restrict__ label4,
    float* __restrict__ out)
{
    const int b = blockIdx.x;
    const int t = threadIdx.x;
    const int base = b * (ROW_L / 4);

    const float4 x = logit4[base + t];
    const int4   y = label4[base + t];

    const float p0 = 1.0f / (1.0f + __expf(-x.x));
    const float p1 = 1.0f / (1.0f + __expf(-x.y));
    const float p2 = 1.0f / (1.0f + __expf(-x.z));
    const float p3 = 1.0f / (1.0f + __expf(-x.w));

    const float fy0 = (float)y.x, fy1 = (float)y.y;
    const float fy2 = (float)y.z, fy3 = (float)y.w;

    float S  = (p0 + p1) + (p2 + p3);                 // sum of all p
    float c1 = (fy0 + fy1) + (fy2 + fy3);             // positive count
    float s1 = fmaf(p0, fy0, fmaf(p1, fy1, fmaf(p2, fy2, p3 * fy3)));  // sum p over positives

    // warp reduce 3 values
    #pragma unroll
    for (int off = 16; off > 0; off >>= 1) {
        S  += __shfl_down_sync(0xFFFFFFFFu, S,  off);
        c1 += __shfl_down_sync(0xFFFFFFFFu, c1, off);
        s1 += __shfl_down_sync(0xFFFFFFFFu, s1, off);
    }

    __shared__ float shS[8], shC[8], sh1[8];
    const int wid = t >> 5;
    const int lid = t & 31;
    if (lid == 0) { shS[wid] = S; shC[wid] = c1; sh1[wid] = s1; }
    __syncthreads();

    if (wid == 0) {
        S  = (lid < (THREADS / 32)) ? shS[lid] : 0.0f;
        c1 = (lid < (THREADS / 32)) ? shC[lid] : 0.0f;
        s1 = (lid < (THREADS / 32)) ? sh1[lid] : 0.0f;
        #pragma unroll
        for (int off = 4; off > 0; off >>= 1) {
            S  += __shfl_down_sync(0xFFFFFFFFu, S,  off);
            c1 += __shfl_down_sync(0xFFFFFFFFu, c1, off);
            s1 += __shfl_down_sync(0xFFFFFFFFu, s1, off);
        }
        if (lid == 0) {
            const float c0 = (float)ROW_L - c1;
            const float s0 = S - s1;
            const float loss = fmaf(c0 * c1, GAMA, fmaf(c1, s0, -c0 * s1));
            atomicAdd(&g_partial, loss);
            __threadfence();
            const unsigned tk = atomicAdd(&g_ticket, 1u);
            if (tk == gridDim.x - 1u) {
                out[0]    = g_partial;   // publish
                g_partial = 0.0f;        // restore clean state for next replay
                g_ticket  = 0u;
            }
        }
    }
}

extern "C" void kernel_launch(void* const* d_in, const int* in_sizes, int n_in,
                              void* d_out, int out_size)
{
    const float4* logit4 = (const float4*)d_in[0];
    const int4*   label4 = (const int4*)d_in[1];
    float* out = (float*)d_out;

    const int B = in_sizes[0] / ROW_L;
    prl_kernel<<<B, THREADS>>>(logit4, label4, out);
}